// round 11
// baseline (speedup 1.0000x reference)
#include <cuda_runtime.h>
#include <cuda_fp16.h>
#include <cstdint>

// ---------------------------------------------------------------------------
// Windowed 3D conv encoder. Per-frame 2D conv decomposition.
// R11: implicit im2col fused into the GEMM loader (cp.async zero-fill for
//      halo), B buffers deleted; F and C2 stored fp16. 128x128 CTA tile,
//      4 warps (warp 64x64), 6 stages, 2 CTAs/SM, split-K 4/3.
// ---------------------------------------------------------------------------

#define K9    9216
#define M1    3072
#define N1R   1568
#define N1P   1664          // 13 * 128
#define M2    1536
#define N2R   4900
#define N2P   4992          // 39 * 128
#define NSLICE 25
#define HW    196
#define BK    32
#define STAGES 6
#define NKP1  4
#define NKP2  3

// ------------------------------------------------------------- scratch -----
__device__ __half d_Vt[8 * HW * 1024];        // video^T: [g*HW+hw][ci] fp16
__device__ __half d_A1[M1 * K9];
__device__ __half d_A2[M2 * K9];
__device__ __half d_F [NKP1 * N1P * M1];      // F^T fp16: [part][n][m]
__device__ __half d_Ht[NSLICE * HW * 1024];   // H^T: [pixel][co] fp16
__device__ __half d_C2[NKP2 * M2 * N2P];      // fp16
__device__ float  d_pool[8 * 512];

// ------------------------------------------------------------ PTX bits -----
__device__ __forceinline__ uint32_t smem_u32(const void* p) {
    uint32_t a;
    asm("{ .reg .u64 t; cvta.to.shared.u64 t, %1; cvt.u32.u64 %0, t; }"
        : "=r"(a) : "l"(p));
    return a;
}
#define CP16(dst, src) \
    asm volatile("cp.async.cg.shared.global [%0], [%1], 16;" \
                 :: "r"(dst), "l"(src))
#define CP16Z(dst, src, sz) \
    asm volatile("cp.async.cg.shared.global [%0], [%1], 16, %2;" \
                 :: "r"(dst), "l"(src), "r"(sz))
#define CPCOMMIT() asm volatile("cp.async.commit_group;" ::: "memory")
#define CPWAIT(n)  asm volatile("cp.async.wait_group %0;" :: "n"(n) : "memory")

#define LDSM4(r0, r1, r2, r3, a) \
    asm volatile("ldmatrix.sync.aligned.m8n8.x4.shared.b16 {%0,%1,%2,%3}, [%4];" \
                 : "=r"(r0), "=r"(r1), "=r"(r2), "=r"(r3) : "r"(a))

#define MMA16816(d, a, b0, b1) \
    asm volatile( \
        "mma.sync.aligned.m16n8k16.row.col.f32.f16.f16.f32 " \
        "{%0,%1,%2,%3},{%4,%5,%6,%7},{%8,%9},{%0,%1,%2,%3};" \
        : "+f"((d)[0]), "+f"((d)[1]), "+f"((d)[2]), "+f"((d)[3]) \
        : "r"((a)[0]), "r"((a)[1]), "r"((a)[2]), "r"((a)[3]), \
          "r"(b0), "r"(b1))

// swizzled byte offset of 16B chunk c in row r (row = 64 bytes = 4 chunks)
__device__ __forceinline__ uint32_t swz(int row, int c) {
    return row * 64 + ((c ^ ((row >> 1) & 3)) << 4);
}

// ---------------------------------------------------- video transpose ------
__global__ void transpose_video_kernel(const float* __restrict__ vid) {
    __shared__ float tile[32][33];
    int g   = blockIdx.x;
    int hw0 = blockIdx.y * 32;
    int ci0 = blockIdx.z * 32;
    int tx = threadIdx.x, ty = threadIdx.y;   // 32 x 8
#pragma unroll
    for (int j = 0; j < 4; j++) {
        int ci = ci0 + ty + 8 * j, hw = hw0 + tx;
        tile[ty + 8 * j][tx] =
            (hw < HW) ? vid[((size_t)g * 1024 + ci) * HW + hw] : 0.0f;
    }
    __syncthreads();
#pragma unroll
    for (int j = 0; j < 4; j++) {
        int hw = hw0 + ty + 8 * j, ci = ci0 + tx;
        if (hw < HW)
            d_Vt[((size_t)g * HW + hw) * 1024 + ci] =
                __float2half_rn(tile[tx][ty + 8 * j]);
    }
}

// ------------------------------------------------------------- packing -----
__global__ void pack_w1_kernel(const float* __restrict__ w) {
    int idx = blockIdx.x * blockDim.x + threadIdx.x;
    if (idx >= 1024 * 1024) return;
    int ci = idx & 1023, co = idx >> 10;
    const float* src = w + (size_t)co * 27648 + ci * 27;
    float v[27];
#pragma unroll
    for (int i = 0; i < 27; i++) v[i] = src[i];
#pragma unroll
    for (int kd = 0; kd < 3; kd++)
#pragma unroll
        for (int r = 0; r < 9; r++)
            d_A1[(size_t)((kd << 10) + co) * K9 + (r << 10) + ci] =
                __float2half_rn(v[kd * 9 + r]);
}

__global__ void pack_w2_kernel(const float* __restrict__ w) {
    int idx = blockIdx.x * blockDim.x + threadIdx.x;
    if (idx >= 512 * 1024) return;
    int ci = idx & 1023, co = idx >> 10;
    const float* src = w + (size_t)co * 27648 + ci * 27;
    float v[27];
#pragma unroll
    for (int i = 0; i < 27; i++) v[i] = src[i];
#pragma unroll
    for (int kd = 0; kd < 3; kd++)
#pragma unroll
        for (int r = 0; r < 9; r++)
            d_A2[(size_t)(kd * 512 + co) * K9 + (r << 10) + ci] =
                __float2half_rn(v[kd * 9 + r]);
}

// --------------------------------------------------------------- GEMM ------
// C(rows x Ncols) = A(rows, k-slice) @ B(Ncols, k-slice)^T, fp16 in/out,
// fp32 accumulate. 128x128 CTA tile, 4 warps as 2x2 (warp 64x64).
// If IMPA: A-slot rows are pixels, loaded implicitly from a [pixel][1024]
// tensor with conv shift per k-band (k = r*1024+ci). IMPB likewise for B.
#define TILE_B    (128 * 64)
#define OFF_A     0
#define OFF_B     (1 * TILE_B)
#define STG_B     (2 * TILE_B)
#define SMEM_TOTAL (STAGES * STG_B)         // 98304

template <bool IMPA, bool IMPB>
__global__ __launch_bounds__(128, 2) void gemm_mma(
    const __half* __restrict__ A, const __half* __restrict__ B,
    __half* __restrict__ C, int Ncols, int limit) {
    const int nparts = gridDim.z;
    const int KPr    = K9 / nparts;
    const int iters  = KPr / BK;
    const int rowsT  = gridDim.y * 128;

    extern __shared__ char smem[];
    const uint32_t smb = smem_u32(smem);
    const int tid  = threadIdx.x;
    const int lane = tid & 31;
    const int wid  = tid >> 5;
    const int wm   = wid >> 1;
    const int wn   = wid & 1;
    const int bym  = blockIdx.y * 128;
    const int bxn  = blockIdx.x * 128;
    const int kbase = blockIdx.z * KPr;

    const __half* pA = IMPA ? A : A + (size_t)bym * K9 + kbase;
    const __half* pB = IMPB ? B : B + (size_t)bxn * K9 + kbase;
    __half* Cp = C + (size_t)blockIdx.z * rowsT * Ncols;

    // loader geometry: 512 chunks per matrix; 128 threads -> 4 per thread.
    int ldRow[4], ldC16[4];
    uint32_t ldDst[4];
#pragma unroll
    for (int t = 0; t < 4; t++) {
        int q = tid + 128 * t;
        ldRow[t] = q >> 2;
        ldC16[t] = q & 3;
        ldDst[t] = swz(ldRow[t], ldC16[t]);
    }

    // implicit-slot per-row pixel geometry
    int py[4], px[4], pok[4];
    const int ib0 = IMPA ? bym : bxn;
    if (IMPA || IMPB) {
#pragma unroll
        for (int t = 0; t < 4; t++) {
            int pix = ib0 + ldRow[t];
            int hw  = pix % HW;
            py[t]  = hw / 14;
            px[t]  = hw % 14;
            pok[t] = (pix < limit);
        }
    }

    auto issue_stage = [&](int stage, int k0) {
        uint32_t sb = smb + stage * STG_B;
        int kg = kbase + k0;
        int r = 0, ci = 0, dpix = 0, kh = 0, kw = 0;
        if (IMPA || IMPB) {
            r  = kg >> 10;
            ci = kg & 1023;
            kh = r / 3 - 1;
            kw = r % 3 - 1;
            dpix = kh * 14 + kw;
        }
#pragma unroll
        for (int t = 0; t < 4; t++) {
            if (IMPA) {
                int v = pok[t] && (unsigned)(py[t] + kh) < 14u
                               && (unsigned)(px[t] + kw) < 14u;
                const __half* src = v
                    ? A + ((size_t)(ib0 + ldRow[t] + dpix)) * 1024
                        + ci + ldC16[t] * 8
                    : A;
                CP16Z(sb + OFF_A + ldDst[t], src, v ? 16 : 0);
            } else {
                CP16(sb + OFF_A + ldDst[t],
                     pA + (size_t)ldRow[t] * K9 + k0 + ldC16[t] * 8);
            }
            if (IMPB) {
                int v = pok[t] && (unsigned)(py[t] + kh) < 14u
                               && (unsigned)(px[t] + kw) < 14u;
                const __half* src = v
                    ? B + ((size_t)(ib0 + ldRow[t] + dpix)) * 1024
                        + ci + ldC16[t] * 8
                    : B;
                CP16Z(sb + OFF_B + ldDst[t], src, v ? 16 : 0);
            } else {
                CP16(sb + OFF_B + ldDst[t],
                     pB + (size_t)ldRow[t] * K9 + k0 + ldC16[t] * 8);
            }
        }
        CPCOMMIT();
    };

    float acc[4][8][4];
#pragma unroll
    for (int mt = 0; mt < 4; mt++)
#pragma unroll
        for (int nt = 0; nt < 8; nt++)
#pragma unroll
            for (int i = 0; i < 4; i++) acc[mt][nt][i] = 0.0f;

    const int a_row = wm * 64 + (lane & 15);
    const int a_c   = lane >> 4;
    const int b_row = wn * 64 + ((lane >> 4) & 1) * 8 + (lane & 7);
    const int b_c   = (lane >> 3) & 1;

#pragma unroll
    for (int s = 0; s < STAGES - 1; s++) issue_stage(s, s * BK);

    int stage = 0;
    for (int it = 0; it < iters; it++) {
        CPWAIT(STAGES - 2);
        __syncthreads();
        if (it + STAGES - 1 < iters) {
            int ws = stage + STAGES - 1; if (ws >= STAGES) ws -= STAGES;
            issue_stage(ws, (it + STAGES - 1) * BK);
        } else {
            CPCOMMIT();
        }

        uint32_t sb = smb + stage * STG_B;
#pragma unroll
        for (int ks = 0; ks < 2; ks++) {
            uint32_t af[4][4];
#pragma unroll
            for (int mt = 0; mt < 4; mt++) {
                uint32_t ao = swz(a_row + mt * 16, ks * 2 + a_c);
                LDSM4(af[mt][0], af[mt][1], af[mt][2], af[mt][3], sb + OFF_A + ao);
            }
#pragma unroll
            for (int g = 0; g < 4; g++) {
                uint32_t bf[4];
                uint32_t bo = swz(b_row + g * 16, ks * 2 + b_c);
                LDSM4(bf[0], bf[1], bf[2], bf[3], sb + OFF_B + bo);
#pragma unroll
                for (int mt = 0; mt < 4; mt++) {
                    MMA16816(acc[mt][2 * g],     af[mt], bf[0], bf[1]);
                    MMA16816(acc[mt][2 * g + 1], af[mt], bf[2], bf[3]);
                }
            }
        }
        if (++stage == STAGES) stage = 0;
    }

    // epilogue: fp32 acc -> fp16 C
#pragma unroll
    for (int mt = 0; mt < 4; mt++) {
        int r0 = bym + wm * 64 + mt * 16 + (lane >> 2);
#pragma unroll
        for (int nt = 0; nt < 8; nt++) {
            int c0 = bxn + wn * 64 + nt * 8 + (lane & 3) * 2;
            __half2 h0 = __floats2half2_rn(acc[mt][nt][0], acc[mt][nt][1]);
            __half2 h1 = __floats2half2_rn(acc[mt][nt][2], acc[mt][nt][3]);
            *(__half2*)(Cp + (size_t)r0 * Ncols + c0) = h0;
            *(__half2*)(Cp + (size_t)(r0 + 8) * Ncols + c0) = h1;
        }
    }
}

// ------------------------------------------------------------- combine -----
// Ht[(s,hw)][co] = relu(b1[co] + sum_e sum_p F^T[p][n_e][kd_e*1024+co]).
// One thread = 8 consecutive co (uint4 fp16 reads/writes).
__global__ void combine1_kernel(const float* __restrict__ b1) {
    int idx = blockIdx.x * blockDim.x + threadIdx.x;
    if (idx >= NSLICE * HW * 128) return;
    int co8 = (idx & 127) << 3;
    int pix = idx >> 7;
    int hw  = pix % HW;
    int s   = pix / HW;

    int kd[3] = {-1, -1, -1};
    int gg[3] = {0, 0, 0};
    if (s < 8)       { kd[0] = 1; gg[0] = s - 4;  kd[1] = 2; gg[1] = s - 3; }
    else if (s < 17) { int g = s - 12;
                       kd[0] = 0; gg[0] = g; kd[1] = 1; gg[1] = g + 1;
                       kd[2] = 2; gg[2] = g + 2; }
    else             { int t = s - 17;
                       kd[0] = 0; gg[0] = t - 2; kd[1] = 1; gg[1] = t - 1; }

    float4 v0 = *(const float4*)(b1 + co8);
    float4 v1 = *(const float4*)(b1 + co8 + 4);
    float acc[8] = {v0.x, v0.y, v0.z, v0.w, v1.x, v1.y, v1.z, v1.w};

#pragma unroll
    for (int e = 0; e < 3; e++) {
        if (kd[e] >= 0 && gg[e] >= 0 && gg[e] < 8) {
            size_t off = ((size_t)gg[e] * HW + hw) * M1 + (kd[e] << 10) + co8;
#pragma unroll
            for (int p = 0; p < NKP1; p++) {
                uint4 f = *(const uint4*)(d_F + (size_t)p * N1P * M1 + off);
                const __half2* h = (const __half2*)&f;
#pragma unroll
                for (int q = 0; q < 4; q++) {
                    float2 fv = __half22float2(h[q]);
                    acc[2 * q]     += fv.x;
                    acc[2 * q + 1] += fv.y;
                }
            }
        }
    }
    uint4 pk;
    __half2* ph = (__half2*)&pk;
#pragma unroll
    for (int q = 0; q < 4; q++)
        ph[q] = __floats2half2_rn(fmaxf(acc[2 * q], 0.0f),
                                  fmaxf(acc[2 * q + 1], 0.0f));
    *(uint4*)&d_Ht[(size_t)pix * 1024 + co8] = pk;
}

// ---------------------------------------------------------------- pool -----
__device__ __forceinline__ float c2sum(int j, int co, size_t idx) {
    size_t off = (size_t)(j * 512 + co) * N2P + idx;
    float v = 0.0f;
#pragma unroll
    for (int p = 0; p < NKP2; p++)
        v += __half2float(d_C2[(size_t)p * M2 * N2P + off]);
    return v;
}

__global__ void pool_kernel(const float* __restrict__ b2) {
    int t  = blockIdx.x >> 9;
    int co = blockIdx.x & 511;
    int s0 = t, s1 = t + 8, s2 = t + 9, s3 = t + 17;

    float m = -1e30f;
    for (int pos = threadIdx.x; pos < 4 * HW; pos += blockDim.x) {
        int d = pos / HW, hw = pos % HW;
        float v;
        if (d == 0)      v = c2sum(1, co, (size_t)s0 * HW + hw)
                           + c2sum(2, co, (size_t)s1 * HW + hw);
        else if (d == 1) v = c2sum(0, co, (size_t)s0 * HW + hw)
                           + c2sum(1, co, (size_t)s1 * HW + hw)
                           + c2sum(2, co, (size_t)s2 * HW + hw);
        else if (d == 2) v = c2sum(0, co, (size_t)s1 * HW + hw)
                           + c2sum(1, co, (size_t)s2 * HW + hw)
                           + c2sum(2, co, (size_t)s3 * HW + hw);
        else             v = c2sum(0, co, (size_t)s2 * HW + hw)
                           + c2sum(1, co, (size_t)s3 * HW + hw);
        m = fmaxf(m, v);
    }
    __shared__ float red[128];
    red[threadIdx.x] = m;
    __syncthreads();
    for (int sft = 64; sft > 0; sft >>= 1) {
        if (threadIdx.x < sft)
            red[threadIdx.x] = fmaxf(red[threadIdx.x], red[threadIdx.x + sft]);
        __syncthreads();
    }
    if (threadIdx.x == 0)
        d_pool[t * 512 + co] = fmaxf(b2[co] + red[0], 0.0f);
}

// ------------------------------------------------------------------ fc -----
__global__ void fc_kernel(const float* __restrict__ w1, const float* __restrict__ b1,
                          const float* __restrict__ w2, const float* __restrict__ b2,
                          const float* __restrict__ w3, const float* __restrict__ b3,
                          float* __restrict__ out) {
    int t = blockIdx.x;
    int j = threadIdx.x;
    __shared__ float x0[512], x1[512];
    x0[j] = d_pool[t * 512 + j];
    __syncthreads();

    float a = b1[j];
#pragma unroll 8
    for (int i = 0; i < 512; i++) a += x0[i] * w1[j * 512 + i];
    x1[j] = fmaxf(a, 0.0f);
    __syncthreads();

    a = b2[j];
#pragma unroll 8
    for (int i = 0; i < 512; i++) a += x1[i] * w2[j * 512 + i];
    __syncthreads();
    x0[j] = fmaxf(a, 0.0f);
    __syncthreads();

    if (j < 128) {
        a = b3[j];
#pragma unroll 8
        for (int i = 0; i < 512; i++) a += x0[i] * w3[j * 512 + i];
        out[t * 128 + j] = fmaxf(a, 0.0f);
    }
}

// -------------------------------------------------------------- launch -----
extern "C" void kernel_launch(void* const* d_in, const int* in_sizes, int n_in,
                              void* d_out, int out_size) {
    auto find = [&](int sz, int occ) -> const float* {
        int c = 0;
        for (int i = 0; i < n_in; i++)
            if (in_sizes[i] == sz) { if (c == occ) return (const float*)d_in[i]; c++; }
        return nullptr;
    };
    const float* videos = find(1605632, 0);
    const float* w1     = find(28311552, 0);
    const float* b1     = find(1024, 0);
    const float* w2     = find(14155776, 0);
    const float* b2     = find(512, 0);
    const float* l1w    = find(262144, 0);
    const float* l1b    = find(512, 1);
    const float* l2w    = find(262144, 1);
    const float* l2b    = find(512, 2);
    const float* l3w    = find(65536, 0);
    const float* l3b    = find(128, 0);
    float* out = (float*)d_out;

    cudaFuncSetAttribute(gemm_mma<true, false>,
                         cudaFuncAttributeMaxDynamicSharedMemorySize, SMEM_TOTAL);
    cudaFuncSetAttribute(gemm_mma<false, true>,
                         cudaFuncAttributeMaxDynamicSharedMemorySize, SMEM_TOTAL);

    const int TB = 256;
    __half *Vtp, *A1p, *A2p, *Htp, *Fp, *C2p;
    cudaGetSymbolAddress((void**)&Vtp, d_Vt);
    cudaGetSymbolAddress((void**)&A1p, d_A1);
    cudaGetSymbolAddress((void**)&A2p, d_A2);
    cudaGetSymbolAddress((void**)&Htp, d_Ht);
    cudaGetSymbolAddress((void**)&Fp,  d_F);
    cudaGetSymbolAddress((void**)&C2p, d_C2);

    transpose_video_kernel<<<dim3(8, 7, 32), dim3(32, 8)>>>(videos);
    pack_w1_kernel<<<(1024 * 1024 + TB - 1) / TB, TB>>>(w1);
    pack_w2_kernel<<<(512 * 1024 + TB - 1) / TB, TB>>>(w2);

    // F^T = Vt(implicit im2col) @ A1^T : rows = pixels (N1P), cols = M1
    gemm_mma<true, false><<<dim3(M1 / 128, N1P / 128, NKP1), 128, SMEM_TOTAL>>>(
        Vtp, A1p, Fp, M1, N1R);

    combine1_kernel<<<(NSLICE * HW * 128 + TB - 1) / TB, TB>>>(b1);

    // C2 = A2 @ Ht(implicit im2col)^T : rows = M2, cols = N2P
    gemm_mma<false, true><<<dim3(N2P / 128, M2 / 128, NKP2), 128, SMEM_TOTAL>>>(
        A2p, Htp, C2p, N2P, N2R);

    pool_kernel<<<8 * 512, 128>>>(b2);
    fc_kernel<<<8, 512>>>(l1w, l1b, l2w, l2b, l3w, l3b, out);
}

// round 12
// speedup vs baseline: 1.0711x; 1.0711x over previous
#include <cuda_runtime.h>
#include <cuda_fp16.h>
#include <cstdint>

// ---------------------------------------------------------------------------
// Windowed 3D conv encoder. Per-frame 2D conv decomposition.
// R12: R10 structure (explicit im2col block copies, lean GEMM loader,
//      127 regs, 2 CTAs/SM) + fp16 F and C2 intermediates (halves epilogue
//      writes and combine/pool reads). 128x128 CTA tile, 4 warps, 6 stages,
//      split-K 4/3.
// ---------------------------------------------------------------------------

#define K9    9216
#define M1    3072
#define N1R   1568
#define N1P   1664          // 13 * 128
#define M2    1536
#define N2R   4900
#define N2P   4992          // 39 * 128
#define NSLICE 25
#define HW    196
#define BK    32
#define STAGES 6
#define NKP1  4
#define NKP2  3

// ------------------------------------------------------------- scratch -----
__device__ __half d_Vt[8 * HW * 1024];        // video^T: [g*HW+hw][ci] fp16
__device__ __half d_A1[M1 * K9];
__device__ __half d_A2[M2 * K9];
__device__ __half d_B1[N1P * K9];
__device__ __half d_B2[N2P * K9];
__device__ __half d_F [NKP1 * N1P * M1];      // F^T fp16: [part][n][m]
__device__ __half d_Ht[NSLICE * HW * 1024];   // H^T: [pixel][co] fp16
__device__ __half d_C2[NKP2 * M2 * N2P];      // fp16
__device__ float  d_pool[8 * 512];

// ------------------------------------------------------------ PTX bits -----
__device__ __forceinline__ uint32_t smem_u32(const void* p) {
    uint32_t a;
    asm("{ .reg .u64 t; cvta.to.shared.u64 t, %1; cvt.u32.u64 %0, t; }"
        : "=r"(a) : "l"(p));
    return a;
}
#define CP16(dst, src) \
    asm volatile("cp.async.cg.shared.global [%0], [%1], 16;" \
                 :: "r"(dst), "l"(src))
#define CPCOMMIT() asm volatile("cp.async.commit_group;" ::: "memory")
#define CPWAIT(n)  asm volatile("cp.async.wait_group %0;" :: "n"(n) : "memory")

#define LDSM4(r0, r1, r2, r3, a) \
    asm volatile("ldmatrix.sync.aligned.m8n8.x4.shared.b16 {%0,%1,%2,%3}, [%4];" \
                 : "=r"(r0), "=r"(r1), "=r"(r2), "=r"(r3) : "r"(a))

#define MMA16816(d, a, b0, b1) \
    asm volatile( \
        "mma.sync.aligned.m16n8k16.row.col.f32.f16.f16.f32 " \
        "{%0,%1,%2,%3},{%4,%5,%6,%7},{%8,%9},{%0,%1,%2,%3};" \
        : "+f"((d)[0]), "+f"((d)[1]), "+f"((d)[2]), "+f"((d)[3]) \
        : "r"((a)[0]), "r"((a)[1]), "r"((a)[2]), "r"((a)[3]), \
          "r"(b0), "r"(b1))

// swizzled byte offset of 16B chunk c in row r (row = 64 bytes = 4 chunks)
__device__ __forceinline__ uint32_t swz(int row, int c) {
    return row * 64 + ((c ^ ((row >> 1) & 3)) << 4);
}

// ---------------------------------------------------- video transpose ------
__global__ void transpose_video_kernel(const float* __restrict__ vid) {
    __shared__ float tile[32][33];
    int g   = blockIdx.x;
    int hw0 = blockIdx.y * 32;
    int ci0 = blockIdx.z * 32;
    int tx = threadIdx.x, ty = threadIdx.y;   // 32 x 8
#pragma unroll
    for (int j = 0; j < 4; j++) {
        int ci = ci0 + ty + 8 * j, hw = hw0 + tx;
        tile[ty + 8 * j][tx] =
            (hw < HW) ? vid[((size_t)g * 1024 + ci) * HW + hw] : 0.0f;
    }
    __syncthreads();
#pragma unroll
    for (int j = 0; j < 4; j++) {
        int hw = hw0 + ty + 8 * j, ci = ci0 + tx;
        if (hw < HW)
            d_Vt[((size_t)g * HW + hw) * 1024 + ci] =
                __float2half_rn(tile[tx][ty + 8 * j]);
    }
}

// ------------------------------------------------------------- packing -----
__global__ void pack_w1_kernel(const float* __restrict__ w) {
    int idx = blockIdx.x * blockDim.x + threadIdx.x;
    if (idx >= 1024 * 1024) return;
    int ci = idx & 1023, co = idx >> 10;
    const float* src = w + (size_t)co * 27648 + ci * 27;
    float v[27];
#pragma unroll
    for (int i = 0; i < 27; i++) v[i] = src[i];
#pragma unroll
    for (int kd = 0; kd < 3; kd++)
#pragma unroll
        for (int r = 0; r < 9; r++)
            d_A1[(size_t)((kd << 10) + co) * K9 + (r << 10) + ci] =
                __float2half_rn(v[kd * 9 + r]);
}

__global__ void pack_w2_kernel(const float* __restrict__ w) {
    int idx = blockIdx.x * blockDim.x + threadIdx.x;
    if (idx >= 512 * 1024) return;
    int ci = idx & 1023, co = idx >> 10;
    const float* src = w + (size_t)co * 27648 + ci * 27;
    float v[27];
#pragma unroll
    for (int i = 0; i < 27; i++) v[i] = src[i];
#pragma unroll
    for (int kd = 0; kd < 3; kd++)
#pragma unroll
        for (int r = 0; r < 9; r++)
            d_A2[(size_t)(kd * 512 + co) * K9 + (r << 10) + ci] =
                __float2half_rn(v[kd * 9 + r]);
}

// ------------------------------------------------------------- im2col ------
// B1[n = g*HW+hw][k = r*1024+ci] = Vt[(g, shifted pixel)][ci] : 16B copies.
__global__ void im2col1_kernel() {
    int idx = blockIdx.x * blockDim.x + threadIdx.x;
    if (idx >= N1P * 9 * 128) return;
    int ci8 = idx & 127;
    int t   = idx >> 7;
    int r   = t % 9;
    int n   = t / 9;
    uint4 val = make_uint4(0, 0, 0, 0);
    if (n < N1R) {
        int g  = n / HW, hw = n % HW;
        int y  = hw / 14, x = hw % 14;
        int kh = r / 3,  kw = r % 3;
        int yy = y + kh - 1, xx = x + kw - 1;
        if (yy >= 0 && yy < 14 && xx >= 0 && xx < 14)
            val = *(const uint4*)&d_Vt[((size_t)g * HW + yy * 14 + xx) * 1024
                                       + ci8 * 8];
    }
    *(uint4*)&d_B1[(size_t)n * K9 + (r << 10) + ci8 * 8] = val;
}

// B2[n][k = r*1024+ci] = Ht[(s, shifted pixel)][ci] : 16B copies.
__global__ void im2col2_kernel() {
    int idx = blockIdx.x * blockDim.x + threadIdx.x;
    if (idx >= N2P * 9 * 128) return;
    int ci8 = idx & 127;
    int t   = idx >> 7;
    int r   = t % 9;
    int n   = t / 9;
    uint4 val = make_uint4(0, 0, 0, 0);
    if (n < N2R) {
        int s  = n / HW, hw = n % HW;
        int y  = hw / 14, x = hw % 14;
        int kh = r / 3,  kw = r % 3;
        int yy = y + kh - 1, xx = x + kw - 1;
        if (yy >= 0 && yy < 14 && xx >= 0 && xx < 14)
            val = *(const uint4*)&d_Ht[((size_t)s * HW + yy * 14 + xx) * 1024
                                       + ci8 * 8];
    }
    *(uint4*)&d_B2[(size_t)n * K9 + (r << 10) + ci8 * 8] = val;
}

// --------------------------------------------------------------- GEMM ------
// C(rows x Ncols) = A(rows, k-slice) @ B(Ncols, k-slice)^T, fp16 in/out,
// fp32 accumulate. 128x128 CTA tile, 4 warps as 2x2 (warp 64x64).
#define TILE_B    (128 * 64)
#define OFF_A     0
#define OFF_B     (1 * TILE_B)
#define STG_B     (2 * TILE_B)
#define SMEM_TOTAL (STAGES * STG_B)         // 98304

__global__ __launch_bounds__(128, 2) void gemm_mma(
    const __half* __restrict__ A, const __half* __restrict__ B,
    __half* __restrict__ C, int Ncols) {
    const int nparts = gridDim.z;
    const int KPr    = K9 / nparts;
    const int iters  = KPr / BK;
    const int rowsT  = gridDim.y * 128;

    extern __shared__ char smem[];
    const uint32_t smb = smem_u32(smem);
    const int tid  = threadIdx.x;
    const int lane = tid & 31;
    const int wid  = tid >> 5;
    const int wm   = wid >> 1;
    const int wn   = wid & 1;
    const int bym  = blockIdx.y * 128;
    const int bxn  = blockIdx.x * 128;
    const int kprt = blockIdx.z;

    const __half* pA = A + (size_t)bym * K9 + (size_t)kprt * KPr;
    const __half* pB = B + (size_t)bxn * K9 + (size_t)kprt * KPr;
    __half* Cp = C + (size_t)kprt * rowsT * Ncols;

    // cp.async geometry: 512 chunks per matrix; 128 threads -> 4 per thread.
    int ldRow[4], ldC16[4];
    uint32_t ldDst[4];
#pragma unroll
    for (int t = 0; t < 4; t++) {
        int q = tid + 128 * t;
        ldRow[t] = q >> 2;
        ldC16[t] = q & 3;
        ldDst[t] = swz(ldRow[t], ldC16[t]);
    }

    auto issue_stage = [&](int stage, int k0) {
        uint32_t sb = smb + stage * STG_B;
#pragma unroll
        for (int t = 0; t < 4; t++) {
            size_t so = (size_t)ldRow[t] * K9 + k0 + ldC16[t] * 8;
            CP16(sb + OFF_A + ldDst[t], pA + so);
            CP16(sb + OFF_B + ldDst[t], pB + so);
        }
        CPCOMMIT();
    };

    float acc[4][8][4];
#pragma unroll
    for (int mt = 0; mt < 4; mt++)
#pragma unroll
        for (int nt = 0; nt < 8; nt++)
#pragma unroll
            for (int i = 0; i < 4; i++) acc[mt][nt][i] = 0.0f;

    const int a_row = wm * 64 + (lane & 15);
    const int a_c   = lane >> 4;
    const int b_row = wn * 64 + ((lane >> 4) & 1) * 8 + (lane & 7);
    const int b_c   = (lane >> 3) & 1;

#pragma unroll
    for (int s = 0; s < STAGES - 1; s++) issue_stage(s, s * BK);

    int stage = 0;
    for (int it = 0; it < iters; it++) {
        CPWAIT(STAGES - 2);
        __syncthreads();
        if (it + STAGES - 1 < iters) {
            int ws = stage + STAGES - 1; if (ws >= STAGES) ws -= STAGES;
            issue_stage(ws, (it + STAGES - 1) * BK);
        } else {
            CPCOMMIT();
        }

        uint32_t sb = smb + stage * STG_B;
#pragma unroll
        for (int ks = 0; ks < 2; ks++) {
            uint32_t af[4][4];
#pragma unroll
            for (int mt = 0; mt < 4; mt++) {
                uint32_t ao = swz(a_row + mt * 16, ks * 2 + a_c);
                LDSM4(af[mt][0], af[mt][1], af[mt][2], af[mt][3], sb + OFF_A + ao);
            }
#pragma unroll
            for (int g = 0; g < 4; g++) {
                uint32_t bf[4];
                uint32_t bo = swz(b_row + g * 16, ks * 2 + b_c);
                LDSM4(bf[0], bf[1], bf[2], bf[3], sb + OFF_B + bo);
#pragma unroll
                for (int mt = 0; mt < 4; mt++) {
                    MMA16816(acc[mt][2 * g],     af[mt], bf[0], bf[1]);
                    MMA16816(acc[mt][2 * g + 1], af[mt], bf[2], bf[3]);
                }
            }
        }
        if (++stage == STAGES) stage = 0;
    }

    // epilogue: fp32 acc -> fp16 C
#pragma unroll
    for (int mt = 0; mt < 4; mt++) {
        int r0 = bym + wm * 64 + mt * 16 + (lane >> 2);
#pragma unroll
        for (int nt = 0; nt < 8; nt++) {
            int c0 = bxn + wn * 64 + nt * 8 + (lane & 3) * 2;
            *(__half2*)(Cp + (size_t)r0 * Ncols + c0) =
                __floats2half2_rn(acc[mt][nt][0], acc[mt][nt][1]);
            *(__half2*)(Cp + (size_t)(r0 + 8) * Ncols + c0) =
                __floats2half2_rn(acc[mt][nt][2], acc[mt][nt][3]);
        }
    }
}

// ------------------------------------------------------------- combine -----
// Ht[(s,hw)][co] = relu(b1[co] + sum_e sum_p F^T[p][n_e][kd_e*1024+co]).
// One thread = 8 consecutive co (uint4 fp16 reads/writes).
__global__ void combine1_kernel(const float* __restrict__ b1) {
    int idx = blockIdx.x * blockDim.x + threadIdx.x;
    if (idx >= NSLICE * HW * 128) return;
    int co8 = (idx & 127) << 3;
    int pix = idx >> 7;
    int hw  = pix % HW;
    int s   = pix / HW;

    int kd[3] = {-1, -1, -1};
    int gg[3] = {0, 0, 0};
    if (s < 8)       { kd[0] = 1; gg[0] = s - 4;  kd[1] = 2; gg[1] = s - 3; }
    else if (s < 17) { int g = s - 12;
                       kd[0] = 0; gg[0] = g; kd[1] = 1; gg[1] = g + 1;
                       kd[2] = 2; gg[2] = g + 2; }
    else             { int t = s - 17;
                       kd[0] = 0; gg[0] = t - 2; kd[1] = 1; gg[1] = t - 1; }

    float4 v0 = *(const float4*)(b1 + co8);
    float4 v1 = *(const float4*)(b1 + co8 + 4);
    float acc[8] = {v0.x, v0.y, v0.z, v0.w, v1.x, v1.y, v1.z, v1.w};

#pragma unroll
    for (int e = 0; e < 3; e++) {
        if (kd[e] >= 0 && gg[e] >= 0 && gg[e] < 8) {
            size_t off = ((size_t)gg[e] * HW + hw) * M1 + (kd[e] << 10) + co8;
#pragma unroll
            for (int p = 0; p < NKP1; p++) {
                uint4 f = *(const uint4*)(d_F + (size_t)p * N1P * M1 + off);
                const __half2* h = (const __half2*)&f;
#pragma unroll
                for (int q = 0; q < 4; q++) {
                    float2 fv = __half22float2(h[q]);
                    acc[2 * q]     += fv.x;
                    acc[2 * q + 1] += fv.y;
                }
            }
        }
    }
    uint4 pk;
    __half2* ph = (__half2*)&pk;
#pragma unroll
    for (int q = 0; q < 4; q++)
        ph[q] = __floats2half2_rn(fmaxf(acc[2 * q], 0.0f),
                                  fmaxf(acc[2 * q + 1], 0.0f));
    *(uint4*)&d_Ht[(size_t)pix * 1024 + co8] = pk;
}

// ---------------------------------------------------------------- pool -----
__device__ __forceinline__ float c2sum(int j, int co, size_t idx) {
    size_t off = (size_t)(j * 512 + co) * N2P + idx;
    float v = 0.0f;
#pragma unroll
    for (int p = 0; p < NKP2; p++)
        v += __half2float(d_C2[(size_t)p * M2 * N2P + off]);
    return v;
}

__global__ void pool_kernel(const float* __restrict__ b2) {
    int t  = blockIdx.x >> 9;
    int co = blockIdx.x & 511;
    int s0 = t, s1 = t + 8, s2 = t + 9, s3 = t + 17;

    float m = -1e30f;
    for (int pos = threadIdx.x; pos < 4 * HW; pos += blockDim.x) {
        int d = pos / HW, hw = pos % HW;
        float v;
        if (d == 0)      v = c2sum(1, co, (size_t)s0 * HW + hw)
                           + c2sum(2, co, (size_t)s1 * HW + hw);
        else if (d == 1) v = c2sum(0, co, (size_t)s0 * HW + hw)
                           + c2sum(1, co, (size_t)s1 * HW + hw)
                           + c2sum(2, co, (size_t)s2 * HW + hw);
        else if (d == 2) v = c2sum(0, co, (size_t)s1 * HW + hw)
                           + c2sum(1, co, (size_t)s2 * HW + hw)
                           + c2sum(2, co, (size_t)s3 * HW + hw);
        else             v = c2sum(0, co, (size_t)s2 * HW + hw)
                           + c2sum(1, co, (size_t)s3 * HW + hw);
        m = fmaxf(m, v);
    }
    __shared__ float red[128];
    red[threadIdx.x] = m;
    __syncthreads();
    for (int sft = 64; sft > 0; sft >>= 1) {
        if (threadIdx.x < sft)
            red[threadIdx.x] = fmaxf(red[threadIdx.x], red[threadIdx.x + sft]);
        __syncthreads();
    }
    if (threadIdx.x == 0)
        d_pool[t * 512 + co] = fmaxf(b2[co] + red[0], 0.0f);
}

// ------------------------------------------------------------------ fc -----
__global__ void fc_kernel(const float* __restrict__ w1, const float* __restrict__ b1,
                          const float* __restrict__ w2, const float* __restrict__ b2,
                          const float* __restrict__ w3, const float* __restrict__ b3,
                          float* __restrict__ out) {
    int t = blockIdx.x;
    int j = threadIdx.x;
    __shared__ float x0[512], x1[512];
    x0[j] = d_pool[t * 512 + j];
    __syncthreads();

    float a = b1[j];
#pragma unroll 8
    for (int i = 0; i < 512; i++) a += x0[i] * w1[j * 512 + i];
    x1[j] = fmaxf(a, 0.0f);
    __syncthreads();

    a = b2[j];
#pragma unroll 8
    for (int i = 0; i < 512; i++) a += x1[i] * w2[j * 512 + i];
    __syncthreads();
    x0[j] = fmaxf(a, 0.0f);
    __syncthreads();

    if (j < 128) {
        a = b3[j];
#pragma unroll 8
        for (int i = 0; i < 512; i++) a += x0[i] * w3[j * 512 + i];
        out[t * 128 + j] = fmaxf(a, 0.0f);
    }
}

// -------------------------------------------------------------- launch -----
extern "C" void kernel_launch(void* const* d_in, const int* in_sizes, int n_in,
                              void* d_out, int out_size) {
    auto find = [&](int sz, int occ) -> const float* {
        int c = 0;
        for (int i = 0; i < n_in; i++)
            if (in_sizes[i] == sz) { if (c == occ) return (const float*)d_in[i]; c++; }
        return nullptr;
    };
    const float* videos = find(1605632, 0);
    const float* w1     = find(28311552, 0);
    const float* b1     = find(1024, 0);
    const float* w2     = find(14155776, 0);
    const float* b2     = find(512, 0);
    const float* l1w    = find(262144, 0);
    const float* l1b    = find(512, 1);
    const float* l2w    = find(262144, 1);
    const float* l2b    = find(512, 2);
    const float* l3w    = find(65536, 0);
    const float* l3b    = find(128, 0);
    float* out = (float*)d_out;

    cudaFuncSetAttribute(gemm_mma, cudaFuncAttributeMaxDynamicSharedMemorySize,
                         SMEM_TOTAL);

    const int TB = 256;
    __half *A1p, *A2p, *B1p, *B2p, *Fp, *C2p;
    cudaGetSymbolAddress((void**)&A1p, d_A1);
    cudaGetSymbolAddress((void**)&A2p, d_A2);
    cudaGetSymbolAddress((void**)&B1p, d_B1);
    cudaGetSymbolAddress((void**)&B2p, d_B2);
    cudaGetSymbolAddress((void**)&Fp,  d_F);
    cudaGetSymbolAddress((void**)&C2p, d_C2);

    transpose_video_kernel<<<dim3(8, 7, 32), dim3(32, 8)>>>(videos);
    pack_w1_kernel<<<(1024 * 1024 + TB - 1) / TB, TB>>>(w1);
    pack_w2_kernel<<<(512 * 1024 + TB - 1) / TB, TB>>>(w2);
    im2col1_kernel<<<(N1P * 9 * 128 + TB - 1) / TB, TB>>>();

    // F^T = B1 @ A1^T : rows = pixels (N1P), cols = M1
    gemm_mma<<<dim3(M1 / 128, N1P / 128, NKP1), 128, SMEM_TOTAL>>>(
        B1p, A1p, Fp, M1);

    combine1_kernel<<<(NSLICE * HW * 128 + TB - 1) / TB, TB>>>(b1);
    im2col2_kernel<<<(N2P * 9 * 128 + TB - 1) / TB, TB>>>();

    // C2 = A2 @ B2^T : rows = M2, cols = N2P
    gemm_mma<<<dim3(N2P / 128, M2 / 128, NKP2), 128, SMEM_TOTAL>>>(
        A2p, B2p, C2p, N2P);

    pool_kernel<<<8 * 512, 128>>>(b2);
    fc_kernel<<<8, 512>>>(l1w, l1b, l2w, l2b, l3w, l3b, out);
}